// round 6
// baseline (speedup 1.0000x reference)
#include <cuda_runtime.h>
#include <cuda_fp16.h>

namespace {

constexpr int BB = 256, TT = 512, DD = 64, HH = 128, KC = 256;
constexpr int TCH = 8;           // pre-kernel t-chunks per batch-pair

// Precomputed per (b,t): q=0 zpre, q=1 rpre, q=2 xmpre(+bh), q=3 delta_h
// Layout [b][t][q][j]  -> 256*512*4*128 floats = 256 MB
__device__ float g_pre[(size_t)BB * TT * 4 * HH];

__device__ __forceinline__ float2 mk2(float x, float y) { return make_float2(x, y); }

// Packed dual-FMA (single FFMA2 issue on sm_103a).
__device__ __forceinline__ void ffma2(float2& d, float2 a, float2 b) {
    asm("{\n\t"
        ".reg .b64 ra, rb, rd;\n\t"
        "mov.b64 ra, {%2, %3};\n\t"
        "mov.b64 rb, {%4, %5};\n\t"
        "mov.b64 rd, {%0, %1};\n\t"
        "fma.rn.f32x2 rd, ra, rb, rd;\n\t"
        "mov.b64 {%0, %1}, rd;\n\t"
        "}"
        : "+f"(d.x), "+f"(d.y)
        : "f"(a.x), "f"(a.y), "f"(b.x), "f"(b.y));
}

__device__ __forceinline__ unsigned pack_h2(float x, float y) {
    __half2 h = __floats2half2_rn(x, y);
    return *reinterpret_cast<unsigned*>(&h);
}
__device__ __forceinline__ float2 unpk(unsigned u) {
    return __half22float2(*reinterpret_cast<__half2*>(&u));
}

// ===========================================================================
// Kernel 1: time-parallel precompute.  grid = 128 pairs x TCH chunks.
// Identical inner structure to R5 (at its broadcast floor); t-chunked for
// better SM fill (7 waves x 1/8 work vs 1 wave x full on 128/148 SMs).
// ===========================================================================
__global__ void __launch_bounds__(512, 1) pre_kernel(
    const float* __restrict__ inp,
    const float* __restrict__ Wgx, const float* __restrict__ bgx,
    const float* __restrict__ Wgh, const float* __restrict__ bgh,
    const float* __restrict__ Wz,  const float* __restrict__ bz,
    const float* __restrict__ Wr,  const float* __restrict__ br,
    const float* __restrict__ Wh,  const float* __restrict__ bh)
{
    __shared__ float axm[2][2][2][128];   // [buf][b][tt][ x(64) | m(64) ]
    __shared__ float ad [2][2][2][64];    // [buf][b][tt][ d ]

    const int tid = threadIdx.x;
    const int b0  = (blockIdx.x & 127) * 2;
    const int t0  = (blockIdx.x >> 7) * (TT / TCH);
    const int q4  = tid >> 7;
    const int j   = tid & 127;

    unsigned wgt[64];
    #pragma unroll
    for (int i = 0; i < 64; ++i) wgt[i] = 0;
    float bias;
    if (q4 <= 1) {
        const float* W = (q4 == 0) ? Wz : Wr;
        #pragma unroll
        for (int i = 0; i < 32; ++i) {
            float2 a = *(const float2*)&W[j * KC + 2 * i];          // x cols
            wgt[i] = pack_h2(a.x, a.y);
            float2 b = *(const float2*)&W[j * KC + 192 + 2 * i];    // m cols
            wgt[32 + i] = pack_h2(b.x, b.y);
        }
        bias = (q4 == 0) ? bz[j] : br[j];
    } else if (q4 == 2) {
        #pragma unroll
        for (int i = 0; i < 32; ++i) {
            float2 a = *(const float2*)&Wh[j * KC + 2 * i];
            wgt[i] = pack_h2(a.x, a.y);
            float2 b = *(const float2*)&Wh[j * KC + 192 + 2 * i];
            wgt[32 + i] = pack_h2(b.x, b.y);
        }
        bias = bh[j];
    } else {
        #pragma unroll
        for (int i = 0; i < 32; ++i) {
            float2 a = *(const float2*)&Wgh[j * DD + 2 * i];
            wgt[i] = pack_h2(a.x, a.y);
        }
        bias = bgh[j];
    }

    const int lb  = (tid >> 7) & 1;
    const int ltt = (tid >> 6) & 1;
    const int ld  = tid & 63;
    float wgxd = 0.f, bgxv = 0.f;
    long lbase = 0;
    if (tid < 256) {
        wgxd  = Wgx[ld * DD + ld];
        bgxv  = bgx[ld];
        lbase = ((long)(b0 + lb) * 4) * TT * DD + ld;
    }
    const long CH = (long)TT * DD;
    float rx = 0.f, rxl = 0.f, rm = 0.f, rd_ = 0.f;
    if (tid < 256) {
        long o = lbase + (long)(t0 + ltt) * DD;
        rx  = inp[o];
        rxl = inp[o + CH];
        rm  = inp[o + 2 * CH];
        rd_ = inp[o + 3 * CH];
    }

    for (int it = 0; it < TT / (2 * TCH); ++it) {
        const int buf = it & 1;
        if (tid < 256) {
            float dx = __expf(-fmaxf(fmaf(rd_, wgxd, bgxv), 0.f));
            float xt = rm * rx + (1.f - rm) * (dx * rxl);
            axm[buf][lb][ltt][ld]      = xt;
            axm[buf][lb][ltt][64 + ld] = rm;
            ad [buf][lb][ltt][ld]      = rd_;
            int tnext = t0 + 2 * (it + 1) + ltt;
            if (tnext > TT - 1) tnext = TT - 1;
            long o = lbase + (long)tnext * DD;
            rx  = inp[o];
            rxl = inp[o + CH];
            rm  = inp[o + 2 * CH];
            rd_ = inp[o + 3 * CH];
        }
        __syncthreads();

        float2 acc[4];
        #pragma unroll
        for (int r = 0; r < 4; ++r) acc[r] = mk2(0.f, 0.f);

        if (q4 < 3) {
            #pragma unroll
            for (int i = 0; i < 32; ++i) {
                float2 w0 = unpk(wgt[2 * i]);
                float2 w1 = unpk(wgt[2 * i + 1]);
                #pragma unroll
                for (int r = 0; r < 4; ++r) {
                    float4 a = *(const float4*)&axm[buf][r >> 1][r & 1][4 * i];
                    ffma2(acc[r], w0, mk2(a.x, a.y));
                    ffma2(acc[r], w1, mk2(a.z, a.w));
                }
            }
        } else {
            #pragma unroll
            for (int i = 0; i < 16; ++i) {
                float2 w0 = unpk(wgt[2 * i]);
                float2 w1 = unpk(wgt[2 * i + 1]);
                #pragma unroll
                for (int r = 0; r < 4; ++r) {
                    float4 a = *(const float4*)&ad[buf][r >> 1][r & 1][4 * i];
                    ffma2(acc[r], w0, mk2(a.x, a.y));
                    ffma2(acc[r], w1, mk2(a.z, a.w));
                }
            }
        }

        #pragma unroll
        for (int r = 0; r < 4; ++r) {
            float v = acc[r].x + acc[r].y + bias;
            if (q4 == 3) v = __expf(-fmaxf(v, 0.f));
            int b = b0 + (r >> 1);
            int t = t0 + 2 * it + (r & 1);
            g_pre[(((size_t)b * TT + t) * 4 + q4) * HH + j] = v;
        }
    }
}

// ===========================================================================
// Kernel 2: sequential scan.  grid=128 (b-pair), NT=512 (16 warps).
// Thread roles keyed off tid bits:
//   A-phase : (gate = tid>>8, kh = (tid>>7)&1, j)  z/r partials, 64 FFMA2
//   reduce  : (rr = tid>>8, b = (tid>>7)&1, j)     rr0 -> z, rr1 -> r,crh
//   C-phase : (khc = tid>>8, bc = (tid>>7)&1, j)   Wh_h partials, 32 FFMA2
//   final   : rr0 threads (b, j)                   tanh + blend + store
// Persistent register weights: 64 u32 per thread (no spill margin at 128).
// ===========================================================================
__global__ void __launch_bounds__(512, 1) scan_kernel(
    const float* __restrict__ Wz, const float* __restrict__ Wr,
    const float* __restrict__ Wh,
    float* __restrict__ out)         // [B,T,H]
{
    __shared__ float hpre[2][HH];    // dh(t) * h(t-1)
    __shared__ float crh [2][HH];    // r * hpre
    __shared__ float zg  [2][HH];
    __shared__ float pZ[2][2][HH];   // [kh][b][j]
    __shared__ float pR[2][2][HH];
    __shared__ float pC[2][2][HH];

    const int tid = threadIdx.x;
    const int b0  = blockIdx.x * 2;
    const int j   = tid & 127;
    const int hi  = tid >> 8;          // gate (A) / rr (reduce,final) / khc (C)
    const int mid = (tid >> 7) & 1;    // kh (A)   / b (reduce,final)  / bc (C)

    // A-phase weights: gate = hi, K-half = mid, over combined cols 64..191
    unsigned wA[32];
    {
        const float* W = hi ? Wr : Wz;
        const int koff = 64 + mid * 64;
        #pragma unroll
        for (int i = 0; i < 32; ++i) {
            float2 a = *(const float2*)&W[j * KC + koff + 2 * i];
            wA[i] = pack_h2(a.x, a.y);
        }
    }
    // C-phase weights: K-half = hi (bc-duplicated across mid)
    unsigned wC[32];
    {
        const int koff = 64 + hi * 64;
        #pragma unroll
        for (int i = 0; i < 32; ++i) {
            float2 a = *(const float2*)&Wh[j * KC + koff + 2 * i];
            wC[i] = pack_h2(a.x, a.y);
        }
    }

    if (tid < 256) hpre[mid][j] = 0.f;

    // scratch streams at [b0+mid][t][q][j]
    const float* pb = &g_pre[((size_t)(b0 + mid) * TT) * 4 * HH + j];
    // cur/nxt: {z, r, xm, dh(t+1)}
    float4 cur, nxt;
    cur = make_float4(pb[0],        pb[HH],        pb[2 * HH],
                      pb[512 + 3 * HH]);                       // dh(1)
    nxt = make_float4(pb[512],      pb[512 + HH],  pb[512 + 2 * HH],
                      pb[1024 + 3 * HH]);                      // dh(2)
    __syncthreads();

    for (int t = 0; t < TT; ++t) {
        // ---- A: z/r partials (gate=hi, K-half=mid, both batches) ----
        {
            const float* h0 = &hpre[0][mid * 64];
            const float* h1 = &hpre[1][mid * 64];
            float2 a0 = mk2(0.f,0.f), a1 = mk2(0.f,0.f);
            float2 c0 = mk2(0.f,0.f), c1 = mk2(0.f,0.f);
            #pragma unroll
            for (int i = 0; i < 16; ++i) {
                float2 w0 = unpk(wA[2 * i]);
                float2 w1 = unpk(wA[2 * i + 1]);
                float4 x0 = *(const float4*)(h0 + 4 * i);
                float4 x1 = *(const float4*)(h1 + 4 * i);
                ffma2(a0, w0, mk2(x0.x, x0.y));
                ffma2(a1, w1, mk2(x0.z, x0.w));
                ffma2(c0, w0, mk2(x1.x, x1.y));
                ffma2(c1, w1, mk2(x1.z, x1.w));
            }
            float* pg = hi ? &pR[mid][0][0] : &pZ[mid][0][0];
            pg[j]      = a0.x + a0.y + a1.x + a1.y;
            pg[HH + j] = c0.x + c0.y + c1.x + c1.y;
        }
        // prefetch scratch for t+2 (and dh for t+3)
        float4 nn;
        {
            int t2 = (t + 2 < TT) ? t + 2 : TT - 1;
            int t3 = (t + 3 < TT) ? t + 3 : TT - 1;
            size_t o = (size_t)t2 * 4 * HH;
            nn = make_float4(pb[o], pb[o + HH], pb[o + 2 * HH],
                             pb[(size_t)t3 * 4 * HH + 3 * HH]);
        }
        __syncthreads();                                   // bar 1

        // ---- reduce: rr0 -> z gate; rr1 -> r gate + crh ----
        if (hi == 0) {
            float zp = pZ[0][mid][j] + pZ[1][mid][j] + cur.x;
            zg[mid][j] = __fdividef(1.f, 1.f + __expf(-zp));
        } else {
            float rp = pR[0][mid][j] + pR[1][mid][j] + cur.y;
            float r  = __fdividef(1.f, 1.f + __expf(-rp));
            crh[mid][j] = r * hpre[mid][j];
        }
        __syncthreads();                                   // bar 2

        // ---- C: Wh_h @ crh (K-half=hi, batch=mid) ----
        {
            const float* cp = &crh[mid][hi * 64];
            float2 a0 = mk2(0.f,0.f), a1 = mk2(0.f,0.f);
            #pragma unroll
            for (int i = 0; i < 16; ++i) {
                float2 w0 = unpk(wC[2 * i]);
                float2 w1 = unpk(wC[2 * i + 1]);
                float4 x0 = *(const float4*)(cp + 4 * i);
                ffma2(a0, w0, mk2(x0.x, x0.y));
                ffma2(a1, w1, mk2(x0.z, x0.w));
            }
            pC[hi][mid][j] = a0.x + a0.y + a1.x + a1.y;
        }
        __syncthreads();                                   // bar 3

        // ---- final: tanh, blend, state + output (rr0 threads) ----
        if (hi == 0) {
            float pre = pC[0][mid][j] + pC[1][mid][j] + cur.z;  // bh in xmpre
            float e2  = __expf(2.f * pre);
            float ht  = 1.f - __fdividef(2.f, e2 + 1.f);        // tanh
            float hp  = hpre[mid][j];
            float hn  = fmaf(zg[mid][j], ht - hp, hp);
            out[((size_t)(b0 + mid) * TT + t) * HH + j] = hn;
            hpre[mid][j] = cur.w * hn;                          // dh(t+1)*h_t
        }
        cur = nxt;
        nxt = nn;
        __syncthreads();                                   // bar 4
    }
}

} // namespace

extern "C" void kernel_launch(void* const* d_in, const int* in_sizes, int n_in,
                              void* d_out, int out_size) {
    const float* inp = (const float*)d_in[0];
    const float* Wgx = (const float*)d_in[1];
    const float* bgx = (const float*)d_in[2];
    const float* Wgh = (const float*)d_in[3];
    const float* bgh = (const float*)d_in[4];
    const float* Wz  = (const float*)d_in[5];
    const float* bz  = (const float*)d_in[6];
    const float* Wr  = (const float*)d_in[7];
    const float* br  = (const float*)d_in[8];
    const float* Wh  = (const float*)d_in[9];
    const float* bh  = (const float*)d_in[10];
    float* out = (float*)d_out;

    pre_kernel<<<(BB / 2) * TCH, 512>>>(inp, Wgx, bgx, Wgh, bgh,
                                        Wz, bz, Wr, br, Wh, bh);
    scan_kernel<<<BB / 2, 512>>>(Wz, Wr, Wh, out);
}